// round 16
// baseline (speedup 1.0000x reference)
#include <cuda_runtime.h>

#define VOCAB 50000
#define EMB   512
#define HID   1024
#define OUTD  4
#define BATCH 128
#define TLEN  256
#define SLAB  (BATCH * HID)

// Scratch (allocation-free rule: __device__ globals).
// RULE (R13-R15 post-mortem): these symbols are ONLY referenced from device
// code. Host passes integers (t, rd, wr); taking a __device__ symbol's
// address in host code is UB and was the cause of three identical failures.
__device__ float g_X0[(size_t)TLEN * SLAB];   // x2h0(emb[fx])+bx0, [t][b][n]
__device__ float g_h0[2][SLAB];               // ping-pong layer-0 hidden
__device__ float g_h1[2][SLAB];               // ping-pong layer-1 hidden

// Accurate tanh immune to --use_fast_math tanh.approx lowering.
__device__ __forceinline__ float tanh_acc(float x) {
    float t = __expf(-2.0f * fabsf(x));
    float r = (1.0f - t) / (1.0f + t);
    return copysignf(r, x);
}

__global__ void init_kernel() {
    int i = blockIdx.x * blockDim.x + threadIdx.x;
    if (i < SLAB) { g_h0[0][i] = 0.0f; g_h1[0][i] = 0.0f; }
}

// ---------------------------------------------------------------------------
// X0 precompute (R11/R12 PASSING kernel, g_X0 written device-side):
// X0[r][n] = sum_k emb[fx[r]][k] * w0[n][k] + b0[n], r = t*128 + b.
// M=32768, N=1024, K=512. BM=64, BN=64, BK=32, 256 threads, 4x4 microtile.
// ---------------------------------------------------------------------------
__global__ __launch_bounds__(256) void embed_gemm_kernel(
    const int* __restrict__ fx, const float* __restrict__ emb,
    const float* __restrict__ w0, const float* __restrict__ b0)
{
    __shared__ float As[32][65];
    __shared__ float Bs[32][65];
    __shared__ int rowfx[64];

    const int tid = threadIdx.x;
    const int m0 = blockIdx.y * 64;
    const int n0 = blockIdx.x * 64;

    if (tid < 64) {
        int r = m0 + tid;
        rowfx[tid] = fx[(r & 127) * TLEN + (r >> 7)];   // fx[b][t], r = t*128+b
    }
    __syncthreads();

    const int ar = tid >> 3;             // 0..31
    const int lk = (tid & 7) << 2;       // 0,4,...,28

    const float* Ap0 = emb + (size_t)rowfx[ar] * EMB + lk;
    const float* Ap1 = emb + (size_t)rowfx[ar + 32] * EMB + lk;
    const float* Bp0 = w0 + (size_t)(n0 + ar) * EMB + lk;
    const float* Bp1 = w0 + (size_t)(n0 + ar + 32) * EMB + lk;

    float4 pa0 = *(const float4*)Ap0;
    float4 pa1 = *(const float4*)Ap1;
    float4 pb0 = *(const float4*)Bp0;
    float4 pb1 = *(const float4*)Bp1;

    const int tm = tid >> 4;
    const int tn = tid & 15;
    float acc[4][4] = {};

    const int NT = EMB / 32;             // 16
    for (int kt = 0; kt < NT; kt++) {
        As[lk+0][ar]    = pa0.x; As[lk+1][ar]    = pa0.y; As[lk+2][ar]    = pa0.z; As[lk+3][ar]    = pa0.w;
        As[lk+0][ar+32] = pa1.x; As[lk+1][ar+32] = pa1.y; As[lk+2][ar+32] = pa1.z; As[lk+3][ar+32] = pa1.w;
        Bs[lk+0][ar]    = pb0.x; Bs[lk+1][ar]    = pb0.y; Bs[lk+2][ar]    = pb0.z; Bs[lk+3][ar]    = pb0.w;
        Bs[lk+0][ar+32] = pb1.x; Bs[lk+1][ar+32] = pb1.y; Bs[lk+2][ar+32] = pb1.z; Bs[lk+3][ar+32] = pb1.w;
        __syncthreads();
        if (kt + 1 < NT) {
            int ko = (kt + 1) * 32;
            pa0 = *(const float4*)(Ap0 + ko);
            pa1 = *(const float4*)(Ap1 + ko);
            pb0 = *(const float4*)(Bp0 + ko);
            pb1 = *(const float4*)(Bp1 + ko);
        }
        #pragma unroll
        for (int kk = 0; kk < 32; kk++) {
            float a0 = As[kk][(tm<<2)+0], a1 = As[kk][(tm<<2)+1];
            float a2 = As[kk][(tm<<2)+2], a3 = As[kk][(tm<<2)+3];
            float c0 = Bs[kk][(tn<<2)+0], c1 = Bs[kk][(tn<<2)+1];
            float c2 = Bs[kk][(tn<<2)+2], c3 = Bs[kk][(tn<<2)+3];
            acc[0][0] = fmaf(a0,c0,acc[0][0]); acc[0][1] = fmaf(a0,c1,acc[0][1]);
            acc[0][2] = fmaf(a0,c2,acc[0][2]); acc[0][3] = fmaf(a0,c3,acc[0][3]);
            acc[1][0] = fmaf(a1,c0,acc[1][0]); acc[1][1] = fmaf(a1,c1,acc[1][1]);
            acc[1][2] = fmaf(a1,c2,acc[1][2]); acc[1][3] = fmaf(a1,c3,acc[1][3]);
            acc[2][0] = fmaf(a2,c0,acc[2][0]); acc[2][1] = fmaf(a2,c1,acc[2][1]);
            acc[2][2] = fmaf(a2,c2,acc[2][2]); acc[2][3] = fmaf(a2,c3,acc[2][3]);
            acc[3][0] = fmaf(a3,c0,acc[3][0]); acc[3][1] = fmaf(a3,c1,acc[3][1]);
            acc[3][2] = fmaf(a3,c2,acc[3][2]); acc[3][3] = fmaf(a3,c3,acc[3][3]);
        }
        __syncthreads();
    }

    #pragma unroll
    for (int i = 0; i < 4; i++) {
        int m = m0 + (tm << 2) + i;
        #pragma unroll
        for (int j = 0; j < 4; j++) {
            int n = n0 + (tn << 2) + j;
            g_X0[(size_t)m * HID + n] = acc[i][j] + b0[n];
        }
    }
}

// ---------------------------------------------------------------------------
// RNN step GEMM, in-CTA K-split-4. All __device__ globals resolved HERE.
// LAYER 0 (KTOT=1024): g_h0[wr] = tanh(g_h0[rd] @ W0^T + X0[t] + bias1)
// LAYER 1 (KTOT=2048): g_h1[wr] = tanh([g_h0[wr], g_h1[rd]] @ [W0;W1]^T
//                                      + bias1 + bias2)
// Tile 32x32 per CTA, grid (32,4) = 128 CTAs, 256 threads = 4 groups x 64.
// Each group owns KTOT/4 of the K-range, 4x4 microtile (8 FMA per LDS word).
// Partials combined in fixed group order (deterministic).
// ---------------------------------------------------------------------------
template <int LAYER>
__global__ __launch_bounds__(256) void rnn_step(
    const float* __restrict__ W0, const float* __restrict__ W1,
    const float* __restrict__ bias1, const float* __restrict__ bias2,
    int t, int rd, int wr)
{
    constexpr int KTOT   = (LAYER == 0) ? 1024 : 2048;
    constexpr int KG     = KTOT / 4;     // k per group: 256 or 512
    constexpr int NTILES = KG / 32;      // 8 or 16

    __shared__ __align__(16) float As[4][32][36];   // [group][k][m]
    __shared__ __align__(16) float Bs[4][32][36];   // [group][k][n]

    const int tid = threadIdx.x;
    const int g   = tid >> 6;            // 0..3
    const int l   = tid & 63;
    const int m0  = blockIdx.y * 32;
    const int n0  = blockIdx.x * 32;
    const int kbase = g * KG;

    // Device-side source selection (compile-time pruned per LAYER)
    const float* Asrc;
    const float* Wsrc;
    int koff;
    if (LAYER == 1 && kbase >= 1024) {
        Asrc = g_h1[rd]; Wsrc = W1; koff = kbase - 1024;
    } else {
        Asrc = (LAYER == 0) ? g_h0[rd] : g_h0[wr];
        Wsrc = W0; koff = kbase;
    }
    float* outp = (LAYER == 0) ? g_h0[wr] : g_h1[wr];

    // Loads: thread covers row = l&31, k-chunk 16*(l>>5) + 0..15
    const int row  = l & 31;
    const int hi16 = (l >> 5) << 4;
    const float* Ap = Asrc + (size_t)(m0 + row) * HID + koff + hi16;
    const float* Bp = Wsrc + (size_t)(n0 + row) * HID + koff + hi16;

    float4 pa[4], pb[4];
    #pragma unroll
    for (int c = 0; c < 4; c++) {
        pa[c] = *(const float4*)(Ap + 4 * c);
        pb[c] = *(const float4*)(Bp + 4 * c);
    }

    const int tm = l >> 3;               // 0..7 -> rows 4*tm
    const int tn = l & 7;                // 0..7 -> cols 4*tn
    float acc[4][4] = {};

    for (int kt = 0; kt < NTILES; kt++) {
        #pragma unroll
        for (int c = 0; c < 4; c++) {
            As[g][hi16 + 4*c + 0][row] = pa[c].x;
            As[g][hi16 + 4*c + 1][row] = pa[c].y;
            As[g][hi16 + 4*c + 2][row] = pa[c].z;
            As[g][hi16 + 4*c + 3][row] = pa[c].w;
            Bs[g][hi16 + 4*c + 0][row] = pb[c].x;
            Bs[g][hi16 + 4*c + 1][row] = pb[c].y;
            Bs[g][hi16 + 4*c + 2][row] = pb[c].z;
            Bs[g][hi16 + 4*c + 3][row] = pb[c].w;
        }
        __syncthreads();
        if (kt + 1 < NTILES) {
            int ko = (kt + 1) * 32;
            #pragma unroll
            for (int c = 0; c < 4; c++) {
                pa[c] = *(const float4*)(Ap + ko + 4 * c);
                pb[c] = *(const float4*)(Bp + ko + 4 * c);
            }
        }
        #pragma unroll
        for (int kk = 0; kk < 32; kk++) {
            float4 av = *(const float4*)&As[g][kk][tm << 2];
            float4 bv = *(const float4*)&Bs[g][kk][tn << 2];
            acc[0][0] = fmaf(av.x, bv.x, acc[0][0]); acc[0][1] = fmaf(av.x, bv.y, acc[0][1]);
            acc[0][2] = fmaf(av.x, bv.z, acc[0][2]); acc[0][3] = fmaf(av.x, bv.w, acc[0][3]);
            acc[1][0] = fmaf(av.y, bv.x, acc[1][0]); acc[1][1] = fmaf(av.y, bv.y, acc[1][1]);
            acc[1][2] = fmaf(av.y, bv.z, acc[1][2]); acc[1][3] = fmaf(av.y, bv.w, acc[1][3]);
            acc[2][0] = fmaf(av.z, bv.x, acc[2][0]); acc[2][1] = fmaf(av.z, bv.y, acc[2][1]);
            acc[2][2] = fmaf(av.z, bv.z, acc[2][2]); acc[2][3] = fmaf(av.z, bv.w, acc[2][3]);
            acc[3][0] = fmaf(av.w, bv.x, acc[3][0]); acc[3][1] = fmaf(av.w, bv.y, acc[3][1]);
            acc[3][2] = fmaf(av.w, bv.z, acc[3][2]); acc[3][3] = fmaf(av.w, bv.w, acc[3][3]);
        }
        __syncthreads();
    }

    // Combine K-split partials in fixed order. Reuse As as scratch:
    // need 3*64*16 = 3072 floats; As holds 4608. The loop above ended on a
    // __syncthreads(), so all As reads are complete.
    float* red = &As[0][0][0];
    if (g >= 1) {
        #pragma unroll
        for (int i = 0; i < 4; i++)
            #pragma unroll
            for (int j = 0; j < 4; j++)
                red[(((g - 1) << 6) + l) * 16 + (i << 2) + j] = acc[i][j];
    }
    __syncthreads();

    if (g == 0) {
        #pragma unroll
        for (int p = 0; p < 3; p++)
            #pragma unroll
            for (int i = 0; i < 4; i++)
                #pragma unroll
                for (int j = 0; j < 4; j++)
                    acc[i][j] += red[((p << 6) + l) * 16 + (i << 2) + j];

        const int n = n0 + (tn << 2);
        float4 bsum = *(const float4*)&bias1[n];
        if (LAYER == 1) {
            float4 b2v = *(const float4*)&bias2[n];
            bsum.x += b2v.x; bsum.y += b2v.y; bsum.z += b2v.z; bsum.w += b2v.w;
        }
        const float* extra = g_X0 + (size_t)t * SLAB;   // LAYER 0 only
        #pragma unroll
        for (int i = 0; i < 4; i++) {
            size_t idx = (size_t)(m0 + (tm << 2) + i) * HID + n;
            float4 e = (LAYER == 0) ? *(const float4*)&extra[idx]
                                    : make_float4(0.f, 0.f, 0.f, 0.f);
            float4 v;
            v.x = tanh_acc(acc[i][0] + e.x + bsum.x);
            v.y = tanh_acc(acc[i][1] + e.y + bsum.y);
            v.z = tanh_acc(acc[i][2] + e.z + bsum.z);
            v.w = tanh_acc(acc[i][3] + e.w + bsum.w);
            *(float4*)&outp[idx] = v;
        }
    }
}

// ---------------------------------------------------------------------------
// Final projection: out[b][o] = h1_final[b] . fc_w[o] + fc_b[o]
// h1_final lives in g_h1[0] (t=255: wr = (255&1)^1 = 0), resolved device-side.
// ---------------------------------------------------------------------------
__global__ __launch_bounds__(128) void fc_kernel(
    const float* __restrict__ fcw, const float* __restrict__ fcb,
    float* __restrict__ out)
{
    const int b = blockIdx.x;
    const int tid = threadIdx.x;
    const float* h = g_h1[0] + (size_t)b * HID;

    float a0 = 0.f, a1 = 0.f, a2 = 0.f, a3 = 0.f;
    for (int k = tid; k < HID; k += 128) {
        float hv = h[k];
        a0 = fmaf(hv, fcw[0 * HID + k], a0);
        a1 = fmaf(hv, fcw[1 * HID + k], a1);
        a2 = fmaf(hv, fcw[2 * HID + k], a2);
        a3 = fmaf(hv, fcw[3 * HID + k], a3);
    }
    __shared__ float red[4][128];
    red[0][tid] = a0; red[1][tid] = a1; red[2][tid] = a2; red[3][tid] = a3;
    __syncthreads();
    for (int s = 64; s > 0; s >>= 1) {
        if (tid < s) {
            #pragma unroll
            for (int o = 0; o < 4; o++) red[o][tid] += red[o][tid + s];
        }
        __syncthreads();
    }
    if (tid < 4) out[b * OUTD + tid] = red[tid][0] + fcb[tid];
}

// ---------------------------------------------------------------------------
extern "C" void kernel_launch(void* const* d_in, const int* in_sizes, int n_in,
                              void* d_out, int out_size) {
    (void)in_sizes; (void)n_in; (void)out_size;
    const int*   fx     = (const int*)  d_in[0];
    const float* emb    = (const float*)d_in[1];
    const float* x2h_w0 = (const float*)d_in[2];
    const float* x2h_b0 = (const float*)d_in[3];
    const float* h2h_w0 = (const float*)d_in[4];
    const float* h2h_b0 = (const float*)d_in[5];
    const float* x2h_w1 = (const float*)d_in[6];
    const float* x2h_b1 = (const float*)d_in[7];
    const float* h2h_w1 = (const float*)d_in[8];
    const float* h2h_b1 = (const float*)d_in[9];
    const float* fc_w   = (const float*)d_in[10];
    const float* fc_b   = (const float*)d_in[11];
    float* out = (float*)d_out;

    init_kernel<<<(SLAB + 255) / 256, 256>>>();

    // X0[t][b][:] = x2h0(emb[fx[b][t]]) + bx0   (off the sequential path)
    embed_gemm_kernel<<<dim3(HID / 64, (BATCH * TLEN) / 64), 256>>>(
        fx, emb, x2h_w0, x2h_b0);

    const dim3 stepGrid(HID / 32, BATCH / 32);   // (32, 4) = 128 CTAs

    for (int t = 0; t < TLEN; t++) {
        int rd = t & 1, wr = rd ^ 1;
        // h0' = tanh(h0 @ Wh0^T + X0[t] + bh0)
        rnn_step<0><<<stepGrid, 256>>>(h2h_w0, h2h_w0, h2h_b0, h2h_b0, t, rd, wr);
        // h1' = tanh([h0', h1] @ [Wx1; Wh1]^T + bx1 + bh1)
        rnn_step<1><<<stepGrid, 256>>>(x2h_w1, h2h_w1, x2h_b1, h2h_b1, t, rd, wr);
    }

    fc_kernel<<<BATCH, 128>>>(fc_w, fc_b, out);
}

// round 17
// speedup vs baseline: 1.3703x; 1.3703x over previous
#include <cuda_runtime.h>

#define VOCAB 50000
#define EMB   512
#define HID   1024
#define OUTD  4
#define BATCH 128
#define TLEN  256
#define SLAB  (BATCH * HID)

// Scratch (allocation-free rule: __device__ globals).
// RULE (R13-R15 post-mortem): these symbols are ONLY referenced from device
// code. Host passes integers; taking a __device__ symbol's address in host
// code is UB and caused three identical failures.
__device__ float g_X0[(size_t)TLEN * SLAB];   // x2h0(emb[fx])+bx0, [t][b][n]
__device__ float g_h0[2][SLAB];               // ping-pong layer-0 hidden
__device__ float g_h1[2][SLAB];               // ping-pong layer-1 hidden

// Accurate tanh immune to --use_fast_math tanh.approx lowering.
__device__ __forceinline__ float tanh_acc(float x) {
    float t = __expf(-2.0f * fabsf(x));
    float r = (1.0f - t) / (1.0f + t);
    return copysignf(r, x);
}

__global__ void init_kernel() {
    int i = blockIdx.x * blockDim.x + threadIdx.x;
    if (i < SLAB) { g_h0[0][i] = 0.0f; g_h1[0][i] = 0.0f; }
}

// ---------------------------------------------------------------------------
// X0 precompute (passing since R11):
// X0[r][n] = sum_k emb[fx[r]][k] * w0[n][k] + b0[n], r = t*128 + b.
// M=32768, N=1024, K=512. BM=64, BN=64, BK=32, 256 threads, 4x4 microtile.
// ---------------------------------------------------------------------------
__global__ __launch_bounds__(256) void embed_gemm_kernel(
    const int* __restrict__ fx, const float* __restrict__ emb,
    const float* __restrict__ w0, const float* __restrict__ b0)
{
    __shared__ float As[32][65];
    __shared__ float Bs[32][65];
    __shared__ int rowfx[64];

    const int tid = threadIdx.x;
    const int m0 = blockIdx.y * 64;
    const int n0 = blockIdx.x * 64;

    if (tid < 64) {
        int r = m0 + tid;
        rowfx[tid] = fx[(r & 127) * TLEN + (r >> 7)];   // fx[b][t], r = t*128+b
    }
    __syncthreads();

    const int ar = tid >> 3;             // 0..31
    const int lk = (tid & 7) << 2;       // 0,4,...,28

    const float* Ap0 = emb + (size_t)rowfx[ar] * EMB + lk;
    const float* Ap1 = emb + (size_t)rowfx[ar + 32] * EMB + lk;
    const float* Bp0 = w0 + (size_t)(n0 + ar) * EMB + lk;
    const float* Bp1 = w0 + (size_t)(n0 + ar + 32) * EMB + lk;

    float4 pa0 = *(const float4*)Ap0;
    float4 pa1 = *(const float4*)Ap1;
    float4 pb0 = *(const float4*)Bp0;
    float4 pb1 = *(const float4*)Bp1;

    const int tm = tid >> 4;
    const int tn = tid & 15;
    float acc[4][4] = {};

    const int NT = EMB / 32;             // 16
    for (int kt = 0; kt < NT; kt++) {
        As[lk+0][ar]    = pa0.x; As[lk+1][ar]    = pa0.y; As[lk+2][ar]    = pa0.z; As[lk+3][ar]    = pa0.w;
        As[lk+0][ar+32] = pa1.x; As[lk+1][ar+32] = pa1.y; As[lk+2][ar+32] = pa1.z; As[lk+3][ar+32] = pa1.w;
        Bs[lk+0][ar]    = pb0.x; Bs[lk+1][ar]    = pb0.y; Bs[lk+2][ar]    = pb0.z; Bs[lk+3][ar]    = pb0.w;
        Bs[lk+0][ar+32] = pb1.x; Bs[lk+1][ar+32] = pb1.y; Bs[lk+2][ar+32] = pb1.z; Bs[lk+3][ar+32] = pb1.w;
        __syncthreads();
        if (kt + 1 < NT) {
            int ko = (kt + 1) * 32;
            pa0 = *(const float4*)(Ap0 + ko);
            pa1 = *(const float4*)(Ap1 + ko);
            pb0 = *(const float4*)(Bp0 + ko);
            pb1 = *(const float4*)(Bp1 + ko);
        }
        #pragma unroll
        for (int kk = 0; kk < 32; kk++) {
            float a0 = As[kk][(tm<<2)+0], a1 = As[kk][(tm<<2)+1];
            float a2 = As[kk][(tm<<2)+2], a3 = As[kk][(tm<<2)+3];
            float c0 = Bs[kk][(tn<<2)+0], c1 = Bs[kk][(tn<<2)+1];
            float c2 = Bs[kk][(tn<<2)+2], c3 = Bs[kk][(tn<<2)+3];
            acc[0][0] = fmaf(a0,c0,acc[0][0]); acc[0][1] = fmaf(a0,c1,acc[0][1]);
            acc[0][2] = fmaf(a0,c2,acc[0][2]); acc[0][3] = fmaf(a0,c3,acc[0][3]);
            acc[1][0] = fmaf(a1,c0,acc[1][0]); acc[1][1] = fmaf(a1,c1,acc[1][1]);
            acc[1][2] = fmaf(a1,c2,acc[1][2]); acc[1][3] = fmaf(a1,c3,acc[1][3]);
            acc[2][0] = fmaf(a2,c0,acc[2][0]); acc[2][1] = fmaf(a2,c1,acc[2][1]);
            acc[2][2] = fmaf(a2,c2,acc[2][2]); acc[2][3] = fmaf(a2,c3,acc[2][3]);
            acc[3][0] = fmaf(a3,c0,acc[3][0]); acc[3][1] = fmaf(a3,c1,acc[3][1]);
            acc[3][2] = fmaf(a3,c2,acc[3][2]); acc[3][3] = fmaf(a3,c3,acc[3][3]);
        }
        __syncthreads();
    }

    #pragma unroll
    for (int i = 0; i < 4; i++) {
        int m = m0 + (tm << 2) + i;
        #pragma unroll
        for (int j = 0; j < 4; j++) {
            int n = n0 + (tn << 2) + j;
            g_X0[(size_t)m * HID + n] = acc[i][j] + b0[n];
        }
    }
}

// ---------------------------------------------------------------------------
// GEMM core (proven R16 code + kk+1 register prefetch), shared by both layers.
// Computes a 32x32 tile of tanh(A @ W^T [+X0] + bias) with in-CTA K-split-4.
// LAYER 0 (KTOT=1024): A = g_h0[rd], W = W0, extra = X0[t], out = g_h0[wr]
// LAYER 1 (KTOT=2048): A = [g_h0[wr], g_h1[rd]], W = [W0;W1], out = g_h1[wr]
// ---------------------------------------------------------------------------
template <int LAYER>
__device__ __forceinline__ void gemm_core(
    float (*As)[32][36], float (*Bs)[32][36],
    const float* __restrict__ W0, const float* __restrict__ W1,
    const float* __restrict__ bias1, const float* __restrict__ bias2,
    int t, int rd, int wr)
{
    constexpr int KTOT   = (LAYER == 0) ? 1024 : 2048;
    constexpr int KG     = KTOT / 4;     // 256 or 512
    constexpr int NTILES = KG / 32;      // 8 or 16

    const int tid = threadIdx.x;
    const int g   = tid >> 6;            // 0..3
    const int l   = tid & 63;
    const int m0  = blockIdx.y * 32;
    const int n0  = blockIdx.x * 32;
    const int kbase = g * KG;

    const float* Asrc;
    const float* Wsrc;
    int koff;
    if (LAYER == 1 && kbase >= 1024) {
        Asrc = g_h1[rd]; Wsrc = W1; koff = kbase - 1024;
    } else {
        Asrc = (LAYER == 0) ? g_h0[rd] : g_h0[wr];
        Wsrc = W0; koff = kbase;
    }
    float* outp = (LAYER == 0) ? g_h0[wr] : g_h1[wr];

    const int row  = l & 31;
    const int hi16 = (l >> 5) << 4;
    const float* Ap = Asrc + (size_t)(m0 + row) * HID + koff + hi16;
    const float* Bp = Wsrc + (size_t)(n0 + row) * HID + koff + hi16;

    float4 pa[4], pb[4];
    #pragma unroll
    for (int c = 0; c < 4; c++) {
        pa[c] = *(const float4*)(Ap + 4 * c);
        pb[c] = *(const float4*)(Bp + 4 * c);
    }

    const int tm = l >> 3;               // 0..7 -> rows 4*tm
    const int tn = l & 7;                // 0..7 -> cols 4*tn
    float acc[4][4] = {};

    for (int kt = 0; kt < NTILES; kt++) {
        #pragma unroll
        for (int c = 0; c < 4; c++) {
            As[g][hi16 + 4*c + 0][row] = pa[c].x;
            As[g][hi16 + 4*c + 1][row] = pa[c].y;
            As[g][hi16 + 4*c + 2][row] = pa[c].z;
            As[g][hi16 + 4*c + 3][row] = pa[c].w;
            Bs[g][hi16 + 4*c + 0][row] = pb[c].x;
            Bs[g][hi16 + 4*c + 1][row] = pb[c].y;
            Bs[g][hi16 + 4*c + 2][row] = pb[c].z;
            Bs[g][hi16 + 4*c + 3][row] = pb[c].w;
        }
        __syncthreads();
        if (kt + 1 < NTILES) {
            int ko = (kt + 1) * 32;
            #pragma unroll
            for (int c = 0; c < 4; c++) {
                pa[c] = *(const float4*)(Ap + ko + 4 * c);
                pb[c] = *(const float4*)(Bp + ko + 4 * c);
            }
        }
        // Software-pipelined inner loop: operands for kk+1 prefetched during
        // the FMAs of kk (breaks the LDS(29cyc) -> FMA dependency chain).
        float4 av = *(const float4*)&As[g][0][tm << 2];
        float4 bv = *(const float4*)&Bs[g][0][tn << 2];
        #pragma unroll
        for (int kk = 0; kk < 32; kk++) {
            const int kn = (kk < 31) ? kk + 1 : 31;
            float4 av_n = *(const float4*)&As[g][kn][tm << 2];
            float4 bv_n = *(const float4*)&Bs[g][kn][tn << 2];
            acc[0][0] = fmaf(av.x, bv.x, acc[0][0]); acc[0][1] = fmaf(av.x, bv.y, acc[0][1]);
            acc[0][2] = fmaf(av.x, bv.z, acc[0][2]); acc[0][3] = fmaf(av.x, bv.w, acc[0][3]);
            acc[1][0] = fmaf(av.y, bv.x, acc[1][0]); acc[1][1] = fmaf(av.y, bv.y, acc[1][1]);
            acc[1][2] = fmaf(av.y, bv.z, acc[1][2]); acc[1][3] = fmaf(av.y, bv.w, acc[1][3]);
            acc[2][0] = fmaf(av.z, bv.x, acc[2][0]); acc[2][1] = fmaf(av.z, bv.y, acc[2][1]);
            acc[2][2] = fmaf(av.z, bv.z, acc[2][2]); acc[2][3] = fmaf(av.z, bv.w, acc[2][3]);
            acc[3][0] = fmaf(av.w, bv.x, acc[3][0]); acc[3][1] = fmaf(av.w, bv.y, acc[3][1]);
            acc[3][2] = fmaf(av.w, bv.z, acc[3][2]); acc[3][3] = fmaf(av.w, bv.w, acc[3][3]);
            av = av_n; bv = bv_n;
        }
        __syncthreads();
    }

    // Combine K-split partials in fixed order. Reuse As as scratch:
    // 3*64*16 = 3072 floats <= 4*32*36 = 4608. Loop ended on __syncthreads().
    float* red = &As[0][0][0];
    if (g >= 1) {
        #pragma unroll
        for (int i = 0; i < 4; i++)
            #pragma unroll
            for (int j = 0; j < 4; j++)
                red[(((g - 1) << 6) + l) * 16 + (i << 2) + j] = acc[i][j];
    }
    __syncthreads();

    if (g == 0) {
        #pragma unroll
        for (int p = 0; p < 3; p++)
            #pragma unroll
            for (int i = 0; i < 4; i++)
                #pragma unroll
                for (int j = 0; j < 4; j++)
                    acc[i][j] += red[((p << 6) + l) * 16 + (i << 2) + j];

        const int n = n0 + (tn << 2);
        float4 bsum = *(const float4*)&bias1[n];
        if (LAYER == 1) {
            float4 b2v = *(const float4*)&bias2[n];
            bsum.x += b2v.x; bsum.y += b2v.y; bsum.z += b2v.z; bsum.w += b2v.w;
        }
        const float* extra = g_X0 + (size_t)t * SLAB;   // LAYER 0 only
        #pragma unroll
        for (int i = 0; i < 4; i++) {
            size_t idx = (size_t)(m0 + (tm << 2) + i) * HID + n;
            float4 e = (LAYER == 0) ? *(const float4*)&extra[idx]
                                    : make_float4(0.f, 0.f, 0.f, 0.f);
            float4 v;
            v.x = tanh_acc(acc[i][0] + e.x + bsum.x);
            v.y = tanh_acc(acc[i][1] + e.y + bsum.y);
            v.z = tanh_acc(acc[i][2] + e.z + bsum.z);
            v.w = tanh_acc(acc[i][3] + e.w + bsum.w);
            *(float4*)&outp[idx] = v;
        }
    }
}

// ---------------------------------------------------------------------------
// Pipelined step: launch k runs L0(k) and L1(k-1) CONCURRENTLY.
//   L0(k):  h0(k)   = tanh(h0(k-1) @ Wh0^T + X0[k] + bh0)     [z = 0, k<TLEN]
//   L1(k-1): h1(k-1) = tanh([h0(k-1), h1(k-2)] @ [Wx1;Wh1]^T + bx1+bh1)
//                                                              [z = 1, k>=1]
// Slots: L0 reads h0[k&1], writes h0[(k&1)^1];
//        L1 reads h0[k&1], h1[(k&1)^1], writes h1[k&1] -> no conflicts.
// Grid (32, 4, 2) = 256 CTAs -> 2 CTAs/SM, 16 warps/SM.
// ---------------------------------------------------------------------------
__global__ __launch_bounds__(256) void step_pipe_kernel(
    const float* __restrict__ Wh0, const float* __restrict__ bh0,
    const float* __restrict__ Wx1, const float* __restrict__ Wh1,
    const float* __restrict__ bx1, const float* __restrict__ bh1,
    int k)
{
    __shared__ __align__(16) float As[4][32][36];
    __shared__ __align__(16) float Bs[4][32][36];

    if (blockIdx.z == 0) {
        if (k >= TLEN) return;
        const int t = k, rd = t & 1, wr = rd ^ 1;
        gemm_core<0>(As, Bs, Wh0, Wh0, bh0, bh0, t, rd, wr);
    } else {
        if (k == 0) return;
        const int t = k - 1, rd = t & 1, wr = rd ^ 1;
        gemm_core<1>(As, Bs, Wx1, Wh1, bx1, bh1, t, rd, wr);
    }
}

// ---------------------------------------------------------------------------
// Final projection: out[b][o] = h1_final[b] . fc_w[o] + fc_b[o]
// h1(255) lives in g_h1[0] (launch k=256 writes slot k&1 = 0).
// ---------------------------------------------------------------------------
__global__ __launch_bounds__(128) void fc_kernel(
    const float* __restrict__ fcw, const float* __restrict__ fcb,
    float* __restrict__ out)
{
    const int b = blockIdx.x;
    const int tid = threadIdx.x;
    const float* h = g_h1[0] + (size_t)b * HID;

    float a0 = 0.f, a1 = 0.f, a2 = 0.f, a3 = 0.f;
    for (int k = tid; k < HID; k += 128) {
        float hv = h[k];
        a0 = fmaf(hv, fcw[0 * HID + k], a0);
        a1 = fmaf(hv, fcw[1 * HID + k], a1);
        a2 = fmaf(hv, fcw[2 * HID + k], a2);
        a3 = fmaf(hv, fcw[3 * HID + k], a3);
    }
    __shared__ float red[4][128];
    red[0][tid] = a0; red[1][tid] = a1; red[2][tid] = a2; red[3][tid] = a3;
    __syncthreads();
    for (int s = 64; s > 0; s >>= 1) {
        if (tid < s) {
            #pragma unroll
            for (int o = 0; o < 4; o++) red[o][tid] += red[o][tid + s];
        }
        __syncthreads();
    }
    if (tid < 4) out[b * OUTD + tid] = red[tid][0] + fcb[tid];
}

// ---------------------------------------------------------------------------
extern "C" void kernel_launch(void* const* d_in, const int* in_sizes, int n_in,
                              void* d_out, int out_size) {
    (void)in_sizes; (void)n_in; (void)out_size;
    const int*   fx     = (const int*)  d_in[0];
    const float* emb    = (const float*)d_in[1];
    const float* x2h_w0 = (const float*)d_in[2];
    const float* x2h_b0 = (const float*)d_in[3];
    const float* h2h_w0 = (const float*)d_in[4];
    const float* h2h_b0 = (const float*)d_in[5];
    const float* x2h_w1 = (const float*)d_in[6];
    const float* x2h_b1 = (const float*)d_in[7];
    const float* h2h_w1 = (const float*)d_in[8];
    const float* h2h_b1 = (const float*)d_in[9];
    const float* fc_w   = (const float*)d_in[10];
    const float* fc_b   = (const float*)d_in[11];
    float* out = (float*)d_out;

    init_kernel<<<(SLAB + 255) / 256, 256>>>();

    // X0[t][b][:] = x2h0(emb[fx[b][t]]) + bx0   (off the sequential path)
    embed_gemm_kernel<<<dim3(HID / 64, (BATCH * TLEN) / 64), 256>>>(
        fx, emb, x2h_w0, x2h_b0);

    const dim3 stepGrid(HID / 32, BATCH / 32, 2);   // (32, 4, 2) = 256 CTAs

    // 257 pipelined launches: launch k computes h0(k) and h1(k-1).
    for (int k = 0; k <= TLEN; k++) {
        step_pipe_kernel<<<stepGrid, 256>>>(
            h2h_w0, h2h_b0, x2h_w1, h2h_w1, x2h_b1, h2h_b1, k);
    }

    fc_kernel<<<BATCH, 128>>>(fc_w, fc_b, out);
}